// round 10
// baseline (speedup 1.0000x reference)
#include <cuda_runtime.h>
#include <cstdint>

#define BATCH 8
#define NPTS  4096
#define MPTS  2048
#define FDIM  64
#define KNBR  64
#define NG    (BATCH*MPTS)
#define CAP   256

// output segments (float32): x_out [NG,128] | pos_out [NG,3] | batch_out [NG]
#define XSEG   (NG*128)
#define PBASE  XSEG
#define BBASE  (XSEG + NG*3)
#define TOTSEG (BBASE + NG)

__device__ float  g_q[NG*3];
__device__ float4 g_pos4[BATCH*NPTS];
__device__ volatile int g_prog[BATCH];
__device__ int    g_ctr;

typedef unsigned long long u64;

__device__ __forceinline__ unsigned rmax32(unsigned v) {
    unsigned r;
    asm("redux.sync.max.u32 %0, %1, 0xffffffff;" : "=r"(r) : "r"(v));
    return r;
}
__device__ __forceinline__ u64 pk2(float lo, float hi) {
    u64 r; asm("mov.b64 %0, {%1, %2};" : "=l"(r) : "f"(lo), "f"(hi)); return r;
}
__device__ __forceinline__ void up2(u64 v, float& lo, float& hi) {
    asm("mov.b64 {%0, %1}, %2;" : "=f"(lo), "=f"(hi) : "l"(v));
}
__device__ __forceinline__ u64 fma2(u64 a, u64 b, u64 c) {
    u64 r; asm("fma.rn.f32x2 %0, %1, %2, %3;" : "=l"(r) : "l"(a), "l"(b), "l"(c)); return r;
}
__device__ __forceinline__ void cp16(uint32_t dst, const float4* src) {
    asm volatile("cp.async.cg.shared.global [%0], [%1], 16;" :: "r"(dst), "l"(src));
}
#define CP_COMMIT() asm volatile("cp.async.commit_group;" ::: "memory")
#define CP_WAIT0()  asm volatile("cp.async.wait_group 0;"  ::: "memory")
__device__ __forceinline__ float ldcv(const float* p) {
    float v; asm volatile("ld.global.cv.f32 %0, [%1];" : "=f"(v) : "l"(p)); return v;
}
__device__ __forceinline__ void gbar(int id) {
    asm volatile("bar.sync %0, 256;" :: "r"(id) : "memory");
}

// ---------------- smem layout (float units) ----------------
// shared weights
#define W1T 0          // 64 x 70
#define W2T 4480       // 64 x 66
#define W3T 8704       // 128 x 66
#define B1O 17152
#define B2O 17216
#define B3O 17280
#define WEND 17408
// per-group region (x2), offsets relative to group base
#define GSZ   15440
#define FEATO 0        // 64 x 68 = 4352
#define H1OO  4352     // 64 x 66 = 4224
#define H2OO  8576     // 64 x 66 = 4224
#define ROO   12800    // 16 x 128 = 2048
#define CDO   14848    // 256
#define CIO   15104    // 256 (int)
#define NLO   15360    // 64 (int)
#define MSO   15424    // ints [0]=seq [1]=cnt; floats [4..6]=q
#define SM_TOT (WEND + 2*GSZ)   // 48288 floats = 193,152 B

// ============================================================================
__global__ void __launch_bounds__(256)
init_kernel(const float* __restrict__ pos)
{
    int i = blockIdx.x * 256 + threadIdx.x;
    if (i == 0) g_ctr = 0;
    if (i < BATCH) g_prog[i] = 0;
    if (i < BATCH * NPTS) {
        const float* p = pos + (size_t)i * 3;
        g_pos4[i] = make_float4(p[0], p[1], p[2], 0.0f);
    }
}

// ============================================================================
__global__ void __launch_bounds__(512)
fused_kernel(const float* __restrict__ x, const float* __restrict__ pos,
             const float* __restrict__ W1, const float* __restrict__ b1,
             const float* __restrict__ W2, const float* __restrict__ b2,
             const float* __restrict__ W3, const float* __restrict__ b3,
             float* __restrict__ dout, int out_size)
{
    extern __shared__ float sm[];
    const int tid = threadIdx.x;
    const int grp = tid >> 8;        // 0 or 1
    const int lt  = tid & 255;       // tid within group

    // ---- stage shared weights (all 512 threads) ----
    for (int idx = tid; idx < 67 * 64; idx += 512) {
        int k = idx >> 6, c = idx & 63;
        sm[W1T + c * 70 + k] = W1[idx];
    }
    for (int idx = tid; idx < 64 * 64; idx += 512) {
        int k = idx >> 6, c = idx & 63;
        sm[W2T + c * 66 + k] = W2[idx];
    }
    for (int idx = tid; idx < 64 * 128; idx += 512) {
        int k = idx >> 7, c = idx & 127;
        sm[W3T + c * 66 + k] = W3[idx];
    }
    if (tid < 64)  { sm[B1O + tid] = b1[tid]; sm[B2O + tid] = b2[tid]; }
    if (tid < 128)   sm[B3O + tid] = b3[tid];
    __syncthreads();

    // ======================= producer: FPS (blocks 0..7, all 512 thr) ======
    if (blockIdx.x < BATCH) {
        __shared__ u64 rd2[32];                 // [parity*16 + warp]
        float* sp = sm + WEND;                  // 12288-float compact pos cache
        const int b = blockIdx.x;
        const int lane = tid & 31, w = tid >> 5;
        const float* pb = pos + (size_t)b * NPTS * 3;

        for (int i = tid; i < NPTS * 3; i += 512) sp[i] = pb[i];
        __syncthreads();

        float px[8], py[8], pz[8], md[8];
#pragma unroll
        for (int j = 0; j < 8; j++) {
            int idx = j * 512 + tid;
            px[j] = sp[3*idx]; py[j] = sp[3*idx+1]; pz[j] = sp[3*idx+2];
            md[j] = __int_as_float(0x7f800000);
        }

        if (tid == 0) {
            int g = b * MPTS;
            g_q[3*g] = sp[0]; g_q[3*g+1] = sp[1]; g_q[3*g+2] = sp[2];
            if (out_size >= BBASE) {
                dout[PBASE+3*g] = sp[0]; dout[PBASE+3*g+1] = sp[1]; dout[PBASE+3*g+2] = sp[2];
            }
            if (out_size >= TOTSEG) dout[BBASE+g] = (float)b;
            __threadfence();
            g_prog[b] = 1;
        }
        __syncthreads();

        int cur = 0;
        for (int step = 1; step < MPTS; step++) {
            float lx = sp[3*cur], ly = sp[3*cur+1], lz = sp[3*cur+2];
            float bd = -1.0f; int bi = 0;
#pragma unroll
            for (int j = 0; j < 8; j++) {
                float dx = __fadd_rn(px[j], -lx);
                float dy = __fadd_rn(py[j], -ly);
                float dz = __fadd_rn(pz[j], -lz);
                float d  = __fadd_rn(__fadd_rn(__fmul_rn(dx,dx), __fmul_rn(dy,dy)),
                                     __fmul_rn(dz,dz));
                float m = fminf(md[j], d);
                md[j] = m;
                if (m > bd) { bd = m; bi = j * 512 + tid; }
            }
            unsigned dbits = __float_as_uint(bd);
            unsigned mx   = rmax32(dbits);
            unsigned cand = (dbits == mx) ? (0xFFFFFFFFu - (unsigned)bi) : 0u;
            unsigned cmx  = rmax32(cand);
            if (lane == 0) rd2[(step & 1) * 16 + w] = ((u64)mx << 32) | (u64)cmx;
            __syncthreads();
            const u64* rr = &rd2[(step & 1) * 16];
            u64 best = rr[0];
#pragma unroll
            for (int i = 1; i < 16; i++) { u64 v = rr[i]; if (v > best) best = v; }
            cur = (int)(0xFFFFFFFFu - (unsigned)best);
            if (tid == 0) {
                int g = b * MPTS + step;
                float qx = sp[3*cur], qy = sp[3*cur+1], qz = sp[3*cur+2];
                g_q[3*g] = qx; g_q[3*g+1] = qy; g_q[3*g+2] = qz;
                if (out_size >= BBASE) {
                    dout[PBASE+3*g] = qx; dout[PBASE+3*g+1] = qy; dout[PBASE+3*g+2] = qz;
                }
                if (out_size >= TOTSEG) dout[BBASE+g] = (float)b;
                __threadfence();
                g_prog[b] = step + 1;
            }
        }
        __syncthreads();   // cache region reused by consumer groups below
    }

    // ======================= consumer: two independent 256-thr groups ======
    float* gb  = sm + WEND + grp * GSZ;
    int*   msi = (int*)(gb + MSO);
    float* msf = gb + MSO + 4;
    int*   nl  = (int*)(gb + NLO);
    int*   ci  = (int*)(gb + CIO);
    const int bid = 1 + grp;         // named barrier id per group

    const int rg = lt >> 4;          // 0..15
    const int cg = lt & 15;          // 0..15
    const int e  = lt >> 2, sub = lt & 3;
    const int lane = tid & 31;
    const uint32_t smF = (uint32_t)__cvta_generic_to_shared(gb + FEATO);
    const uint32_t rowoff = (uint32_t)((e * 68 + sub * 16) * sizeof(float));
    const float R2 = (float)(0.15 * 0.15);

    for (;;) {
        if (lt == 0) msi[0] = atomicAdd(&g_ctr, 1);
        gbar(bid);
        const int seq = msi[0];
        if (seq >= NG) break;
        const int m = seq >> 3, b = seq & 7;
        const int g = b * MPTS + m;

        if (lt == 0) {
            while (g_prog[b] <= m) __nanosleep(128);
            __threadfence();
            msf[0] = ldcv(&g_q[3*g]);
            msf[1] = ldcv(&g_q[3*g+1]);
            msf[2] = ldcv(&g_q[3*g+2]);
            msi[1] = 0;
        }
        gbar(bid);
        const float qx = msf[0], qy = msf[1], qz = msf[2];

        // ---- radius candidates (warp-aggregated compaction) ----
#pragma unroll 4
        for (int i = lt; i < NPTS; i += 256) {
            float4 p = g_pos4[b * NPTS + i];
            float dx = __fadd_rn(qx, -p.x);
            float dy = __fadd_rn(qy, -p.y);
            float dz = __fadd_rn(qz, -p.z);
            float d2 = __fadd_rn(__fadd_rn(__fmul_rn(dx,dx), __fmul_rn(dy,dy)),
                                 __fmul_rn(dz,dz));
            bool keep = (d2 <= R2);
            unsigned msk = __ballot_sync(0xffffffffu, keep);
            int basew = 0;
            if (lane == 0 && msk) basew = atomicAdd(&msi[1], __popc(msk));
            basew = __shfl_sync(0xffffffffu, basew, 0);
            if (keep) {
                int ofs = basew + __popc(msk & ((1u << lane) - 1u));
                if (ofs < CAP) { gb[CDO + ofs] = d2; ci[ofs] = i; }
            }
        }
        gbar(bid);
        int cnt = msi[1]; if (cnt > CAP) cnt = CAP;

        // ---- rank-select 64 nearest (stable: smaller d2, then lower idx) ----
        if (cnt > KNBR) {
            for (int t = lt; t < cnt; t += 256) {
                float di = gb[CDO + t]; int ii = ci[t];
                int r = 0;
                for (int j2 = 0; j2 < cnt; j2++) {
                    float dj = gb[CDO + j2];
                    r += (int)((dj < di) | ((dj == di) & (ci[j2] < ii)));
                }
                if (r < KNBR) nl[r] = ii;
            }
        } else {
            for (int t = lt; t < cnt; t += 256) nl[t] = ci[t];
        }
        gbar(bid);
        if (cnt > KNBR) cnt = KNBR;

        // ---- gather feat rows ----
        {
            int j = nl[(e < cnt) ? e : 0];
            const float4* xr = (const float4*)(x + ((size_t)b * NPTS + j) * FDIM) + sub * 4;
            cp16(smF + rowoff +  0, xr + 0);
            cp16(smF + rowoff + 16, xr + 1);
            cp16(smF + rowoff + 32, xr + 2);
            cp16(smF + rowoff + 48, xr + 3);
            CP_COMMIT();
            if (sub == 0) {
                float4 pr = g_pos4[b * NPTS + j];
                gb[FEATO + e*68 + 64] = __fadd_rn(pr.x, -qx);
                gb[FEATO + e*68 + 65] = __fadd_rn(pr.y, -qy);
                gb[FEATO + e*68 + 66] = __fadd_rn(pr.z, -qz);
            }
            CP_WAIT0();
        }
        gbar(bid);

        // ---- layer 1: K=67 (33 k-pairs + scalar k=66) ----
        {
            u64 acc[4][4];
#pragma unroll
            for (int i = 0; i < 4; i++)
#pragma unroll
                for (int j = 0; j < 4; j++)
                    acc[i][j] = pk2(sm[B1O + cg + 16*j], 0.0f);
#pragma unroll 3
            for (int kp = 0; kp < 33; kp++) {
                const int k = 2 * kp;
                u64 a[4];
#pragma unroll
                for (int i = 0; i < 4; i++)
                    a[i] = *(const u64*)(gb + FEATO + (4*rg + i)*68 + k);
#pragma unroll
                for (int j = 0; j < 4; j++) {
                    u64 wv = *(const u64*)(sm + W1T + (cg + 16*j)*70 + k);
#pragma unroll
                    for (int i = 0; i < 4; i++)
                        acc[i][j] = fma2(a[i], wv, acc[i][j]);
                }
            }
#pragma unroll
            for (int i = 0; i < 4; i++) {
                float a66 = gb[FEATO + (4*rg + i)*68 + 66];
#pragma unroll
                for (int j = 0; j < 4; j++) {
                    float lo, hi; up2(acc[i][j], lo, hi);
                    float s = __fadd_rn(lo, hi);
                    s = fmaf(a66, sm[W1T + (cg + 16*j)*70 + 66], s);
                    gb[H1OO + (4*rg + i)*66 + cg + 16*j] = fmaxf(s, 0.0f);
                }
            }
        }
        gbar(bid);

        // ---- layer 2: K=64 ----
        {
            u64 acc[4][4];
#pragma unroll
            for (int i = 0; i < 4; i++)
#pragma unroll
                for (int j = 0; j < 4; j++)
                    acc[i][j] = pk2(sm[B2O + cg + 16*j], 0.0f);
#pragma unroll 2
            for (int kp = 0; kp < 32; kp++) {
                const int k = 2 * kp;
                u64 a[4];
#pragma unroll
                for (int i = 0; i < 4; i++)
                    a[i] = *(const u64*)(gb + H1OO + (4*rg + i)*66 + k);
#pragma unroll
                for (int j = 0; j < 4; j++) {
                    u64 wv = *(const u64*)(sm + W2T + (cg + 16*j)*66 + k);
#pragma unroll
                    for (int i = 0; i < 4; i++)
                        acc[i][j] = fma2(a[i], wv, acc[i][j]);
                }
            }
#pragma unroll
            for (int i = 0; i < 4; i++)
#pragma unroll
                for (int j = 0; j < 4; j++) {
                    float lo, hi; up2(acc[i][j], lo, hi);
                    gb[H2OO + (4*rg + i)*66 + cg + 16*j] =
                        fmaxf(__fadd_rn(lo, hi), 0.0f);
                }
        }
        gbar(bid);

        // ---- layer 3: K=64, 128 cols, relu + max over own 4 rows ----
        {
            u64 acc[4][8];
#pragma unroll
            for (int i = 0; i < 4; i++)
#pragma unroll
                for (int j = 0; j < 8; j++)
                    acc[i][j] = pk2(sm[B3O + cg + 16*j], 0.0f);
#pragma unroll 2
            for (int kp = 0; kp < 32; kp++) {
                const int k = 2 * kp;
                u64 a[4];
#pragma unroll
                for (int i = 0; i < 4; i++)
                    a[i] = *(const u64*)(gb + H2OO + (4*rg + i)*66 + k);
#pragma unroll
                for (int j = 0; j < 8; j++) {
                    u64 wv = *(const u64*)(sm + W3T + (cg + 16*j)*66 + k);
#pragma unroll
                    for (int i = 0; i < 4; i++)
                        acc[i][j] = fma2(a[i], wv, acc[i][j]);
                }
            }
#pragma unroll
            for (int j = 0; j < 8; j++) {
                float lo, hi; up2(acc[0][j], lo, hi);
                float mm = fmaxf(__fadd_rn(lo, hi), 0.0f);
#pragma unroll
                for (int i = 1; i < 4; i++) {
                    up2(acc[i][j], lo, hi);
                    mm = fmaxf(mm, fmaxf(__fadd_rn(lo, hi), 0.0f));
                }
                gb[ROO + rg*128 + cg + 16*j] = mm;
            }
        }
        gbar(bid);

        if (lt < 128) {
            float mm = gb[ROO + lt];
#pragma unroll
            for (int r = 1; r < 16; r++) mm = fmaxf(mm, gb[ROO + r*128 + lt]);
            dout[(size_t)g * 128 + lt] = mm;
        }
        gbar(bid);   // protect smem reuse next iteration
    }
}

// ============================================================================
extern "C" void kernel_launch(void* const* d_in, const int* in_sizes, int n_in,
                              void* d_out, int out_size)
{
    const float* x   = (const float*)d_in[0];
    const float* pos = (const float*)d_in[1];
    const float* W1 = (const float*)d_in[3];
    const float* b1 = (const float*)d_in[4];
    const float* W2 = (const float*)d_in[5];
    const float* b2 = (const float*)d_in[6];
    const float* W3 = (const float*)d_in[7];
    const float* b3 = (const float*)d_in[8];
    float* out = (float*)d_out;

    const int fused_smem = SM_TOT * sizeof(float);   // 193,152 B -> 1 CTA/SM
    cudaFuncSetAttribute(fused_kernel, cudaFuncAttributeMaxDynamicSharedMemorySize,
                         fused_smem);

    init_kernel<<<(BATCH * NPTS + 255) / 256, 256>>>(pos);
    fused_kernel<<<148, 512, fused_smem>>>(x, pos, W1, b1, W2, b2, W3, b3,
                                           out, out_size);
}

// round 11
// speedup vs baseline: 1.0014x; 1.0014x over previous
#include <cuda_runtime.h>
#include <cstdint>

#define BATCH 8
#define NPTS  4096
#define MPTS  2048
#define FDIM  64
#define KNBR  64
#define NG    (BATCH*MPTS)
#define CAP   256

// output segments (float32): x_out [NG,128] | pos_out [NG,3] | batch_out [NG]
#define XSEG   (NG*128)
#define PBASE  XSEG
#define BBASE  (XSEG + NG*3)
#define TOTSEG (BBASE + NG)

__device__ float  g_q[NG*3];
__device__ float4 g_pos4[BATCH*NPTS];
__device__ volatile int g_prog[BATCH];
__device__ int    g_ctr;

typedef unsigned long long u64;

__device__ __forceinline__ unsigned rmax32(unsigned v) {
    unsigned r;
    asm("redux.sync.max.u32 %0, %1, 0xffffffff;" : "=r"(r) : "r"(v));
    return r;
}
__device__ __forceinline__ u64 pk2(float lo, float hi) {
    u64 r; asm("mov.b64 %0, {%1, %2};" : "=l"(r) : "f"(lo), "f"(hi)); return r;
}
__device__ __forceinline__ void up2(u64 v, float& lo, float& hi) {
    asm("mov.b64 {%0, %1}, %2;" : "=f"(lo), "=f"(hi) : "l"(v));
}
__device__ __forceinline__ u64 fma2(u64 a, u64 b, u64 c) {
    u64 r; asm("fma.rn.f32x2 %0, %1, %2, %3;" : "=l"(r) : "l"(a), "l"(b), "l"(c)); return r;
}
__device__ __forceinline__ void cp16(uint32_t dst, const float4* src) {
    asm volatile("cp.async.cg.shared.global [%0], [%1], 16;" :: "r"(dst), "l"(src));
}
#define CP_COMMIT() asm volatile("cp.async.commit_group;" ::: "memory")
#define CP_WAIT0()  asm volatile("cp.async.wait_group 0;"  ::: "memory")
__device__ __forceinline__ float ldcv(const float* p) {
    float v; asm volatile("ld.global.cv.f32 %0, [%1];" : "=f"(v) : "l"(p)); return v;
}
__device__ __forceinline__ void gbar(int id) {
    asm volatile("bar.sync %0, 256;" :: "r"(id) : "memory");
}

// ---------------- smem layout (float units); all strides 68 ----------------
#define W1T 0          // 64 x 68 (row 67 zeroed)
#define W2T 4352       // 64 x 68
#define W3T 8704       // 128 x 68
#define B1O 17408
#define B2O 17472
#define B3O 17536
#define WEND 17664
// per-group region (x2)
#define GSZ   15696
#define FEATO 0        // 64 x 68 (col 67 zeroed)
#define H1OO  4352     // 64 x 68
#define H2OO  8704     // 64 x 68
#define ROO   13056    // 16 x 128 = 2048
#define CDO   15104    // 256
#define CIO   15360    // 256 (int)
#define NLO   15616    // 64 (int)
#define MSO   15680    // ints [0]=seq [1]=cnt; floats [4..6]=q
#define SM_TOT (WEND + 2*GSZ)   // 49056 floats = 196,224 B

// ============================================================================
__global__ void __launch_bounds__(256)
init_kernel(const float* __restrict__ pos)
{
    int i = blockIdx.x * 256 + threadIdx.x;
    if (i == 0) g_ctr = 0;
    if (i < BATCH) g_prog[i] = 0;
    if (i < BATCH * NPTS) {
        const float* p = pos + (size_t)i * 3;
        g_pos4[i] = make_float4(p[0], p[1], p[2], 0.0f);
    }
}

// ============================================================================
__global__ void __launch_bounds__(512)
fused_kernel(const float* __restrict__ x, const float* __restrict__ pos,
             const float* __restrict__ W1, const float* __restrict__ b1,
             const float* __restrict__ W2, const float* __restrict__ b2,
             const float* __restrict__ W3, const float* __restrict__ b3,
             float* __restrict__ dout, int out_size)
{
    extern __shared__ float sm[];
    const int tid = threadIdx.x;
    const int grp = tid >> 8;        // 0 or 1
    const int lt  = tid & 255;       // tid within group

    // ---- stage transposed weights (stride 68) + biases ----
    for (int idx = tid; idx < 67 * 64; idx += 512) {
        int k = idx >> 6, c = idx & 63;
        sm[W1T + c * 68 + k] = W1[idx];
    }
    for (int idx = tid; idx < 64 * 64; idx += 512) {
        int k = idx >> 6, c = idx & 63;
        sm[W2T + c * 68 + k] = W2[idx];
    }
    for (int idx = tid; idx < 64 * 128; idx += 512) {
        int k = idx >> 7, c = idx & 127;
        sm[W3T + c * 68 + k] = W3[idx];
    }
    if (tid < 64) sm[W1T + tid * 68 + 67] = 0.0f;     // zero pad row 67
    if (tid < 64)  { sm[B1O + tid] = b1[tid]; sm[B2O + tid] = b2[tid]; }
    if (tid < 128)   sm[B3O + tid] = b3[tid];
    __syncthreads();

    // ======================= producer: FPS (blocks 0..7, all 512 thr) ======
    if (blockIdx.x < BATCH) {
        __shared__ u64 rd2[32];                 // [parity*16 + warp]
        float* sp = sm + WEND;                  // compact stride-3 pos cache
        const int b = blockIdx.x;
        const int lane = tid & 31, w = tid >> 5;
        const float* pb = pos + (size_t)b * NPTS * 3;

        for (int i = tid; i < NPTS * 3; i += 512) sp[i] = pb[i];
        __syncthreads();

        float px[8], py[8], pz[8], md[8];
#pragma unroll
        for (int j = 0; j < 8; j++) {
            int idx = j * 512 + tid;
            px[j] = sp[3*idx]; py[j] = sp[3*idx+1]; pz[j] = sp[3*idx+2];
            md[j] = __int_as_float(0x7f800000);
        }

        if (tid == 0) {
            int g = b * MPTS;
            g_q[3*g] = sp[0]; g_q[3*g+1] = sp[1]; g_q[3*g+2] = sp[2];
            if (out_size >= BBASE) {
                dout[PBASE+3*g] = sp[0]; dout[PBASE+3*g+1] = sp[1]; dout[PBASE+3*g+2] = sp[2];
            }
            if (out_size >= TOTSEG) dout[BBASE+g] = (float)b;
            __threadfence();
            g_prog[b] = 1;
        }
        __syncthreads();

        int cur = 0;
        for (int step = 1; step < MPTS; step++) {
            float lx = sp[3*cur], ly = sp[3*cur+1], lz = sp[3*cur+2];
            float bd = -1.0f; int bi = 0;
#pragma unroll
            for (int j = 0; j < 8; j++) {
                float dx = __fadd_rn(px[j], -lx);
                float dy = __fadd_rn(py[j], -ly);
                float dz = __fadd_rn(pz[j], -lz);
                float d  = __fadd_rn(__fadd_rn(__fmul_rn(dx,dx), __fmul_rn(dy,dy)),
                                     __fmul_rn(dz,dz));
                float m = fminf(md[j], d);
                md[j] = m;
                if (m > bd) { bd = m; bi = j * 512 + tid; }
            }
            unsigned dbits = __float_as_uint(bd);
            unsigned mx   = rmax32(dbits);
            unsigned cand = (dbits == mx) ? (0xFFFFFFFFu - (unsigned)bi) : 0u;
            unsigned cmx  = rmax32(cand);
            if (lane == 0) rd2[(step & 1) * 16 + w] = ((u64)mx << 32) | (u64)cmx;
            __syncthreads();
            const u64* rr = &rd2[(step & 1) * 16];
            u64 best = rr[0];
#pragma unroll
            for (int i = 1; i < 16; i++) { u64 v = rr[i]; if (v > best) best = v; }
            cur = (int)(0xFFFFFFFFu - (unsigned)best);
            if (tid == 0) {
                int g = b * MPTS + step;
                float qx = sp[3*cur], qy = sp[3*cur+1], qz = sp[3*cur+2];
                g_q[3*g] = qx; g_q[3*g+1] = qy; g_q[3*g+2] = qz;
                if (out_size >= BBASE) {
                    dout[PBASE+3*g] = qx; dout[PBASE+3*g+1] = qy; dout[PBASE+3*g+2] = qz;
                }
                if (out_size >= TOTSEG) dout[BBASE+g] = (float)b;
                __threadfence();
                g_prog[b] = step + 1;
            }
        }
        __syncthreads();   // cache region reused by consumer groups below
    }

    // ======================= consumer: two independent 256-thr groups ======
    float* gb  = sm + WEND + grp * GSZ;
    int*   msi = (int*)(gb + MSO);
    float* msf = gb + MSO + 4;
    int*   nl  = (int*)(gb + NLO);
    int*   ci  = (int*)(gb + CIO);
    const int bid = 1 + grp;         // named barrier id per group

    const int rg = lt >> 4;          // 0..15
    const int cg = lt & 15;          // 0..15
    const int e  = lt >> 2, sub = lt & 3;
    const int lane = tid & 31;
    const uint32_t smF = (uint32_t)__cvta_generic_to_shared(gb + FEATO);
    const uint32_t rowoff = (uint32_t)((e * 68 + sub * 16) * sizeof(float));
    const float R2 = (float)(0.15 * 0.15);

    // zero-pad FEAT col 67 once (after FPS so producer scratch doesn't clobber)
    if (sub == 0) gb[FEATO + e * 68 + 67] = 0.0f;

    for (;;) {
        if (lt == 0) msi[0] = atomicAdd(&g_ctr, 1);
        gbar(bid);
        const int seq = msi[0];
        if (seq >= NG) break;
        const int m = seq >> 3, b = seq & 7;
        const int g = b * MPTS + m;

        if (lt == 0) {
            while (g_prog[b] <= m) __nanosleep(128);
            __threadfence();
            msf[0] = ldcv(&g_q[3*g]);
            msf[1] = ldcv(&g_q[3*g+1]);
            msf[2] = ldcv(&g_q[3*g+2]);
            msi[1] = 0;
        }
        gbar(bid);
        const float qx = msf[0], qy = msf[1], qz = msf[2];

        // ---- radius candidates (warp-aggregated compaction) ----
#pragma unroll 4
        for (int i = lt; i < NPTS; i += 256) {
            float4 p = g_pos4[b * NPTS + i];
            float dx = __fadd_rn(qx, -p.x);
            float dy = __fadd_rn(qy, -p.y);
            float dz = __fadd_rn(qz, -p.z);
            float d2 = __fadd_rn(__fadd_rn(__fmul_rn(dx,dx), __fmul_rn(dy,dy)),
                                 __fmul_rn(dz,dz));
            bool keep = (d2 <= R2);
            unsigned msk = __ballot_sync(0xffffffffu, keep);
            int basew = 0;
            if (lane == 0 && msk) basew = atomicAdd(&msi[1], __popc(msk));
            basew = __shfl_sync(0xffffffffu, basew, 0);
            if (keep) {
                int ofs = basew + __popc(msk & ((1u << lane) - 1u));
                if (ofs < CAP) { gb[CDO + ofs] = d2; ci[ofs] = i; }
            }
        }
        gbar(bid);
        int cnt = msi[1]; if (cnt > CAP) cnt = CAP;

        // ---- rank-select 64 nearest (stable: smaller d2, then lower idx) ----
        if (cnt > KNBR) {
            for (int t = lt; t < cnt; t += 256) {
                float di = gb[CDO + t]; int ii = ci[t];
                int r = 0;
                for (int j2 = 0; j2 < cnt; j2++) {
                    float dj = gb[CDO + j2];
                    r += (int)((dj < di) | ((dj == di) & (ci[j2] < ii)));
                }
                if (r < KNBR) nl[r] = ii;
            }
        } else {
            for (int t = lt; t < cnt; t += 256) nl[t] = ci[t];
        }
        gbar(bid);
        if (cnt > KNBR) cnt = KNBR;

        // ---- gather feat rows ----
        {
            int j = nl[(e < cnt) ? e : 0];
            const float4* xr = (const float4*)(x + ((size_t)b * NPTS + j) * FDIM) + sub * 4;
            cp16(smF + rowoff +  0, xr + 0);
            cp16(smF + rowoff + 16, xr + 1);
            cp16(smF + rowoff + 32, xr + 2);
            cp16(smF + rowoff + 48, xr + 3);
            CP_COMMIT();
            if (sub == 0) {
                float4 pr = g_pos4[b * NPTS + j];
                gb[FEATO + e*68 + 64] = __fadd_rn(pr.x, -qx);
                gb[FEATO + e*68 + 65] = __fadd_rn(pr.y, -qy);
                gb[FEATO + e*68 + 66] = __fadd_rn(pr.z, -qz);
            }
            CP_WAIT0();
        }
        gbar(bid);

        // ---- layer 1: K=68 as 17 float4 rounds (pad contributes a*0=0) ----
        {
            u64 acc[4][4];
#pragma unroll
            for (int i = 0; i < 4; i++)
#pragma unroll
                for (int j = 0; j < 4; j++)
                    acc[i][j] = pk2(sm[B1O + cg + 16*j], 0.0f);
#pragma unroll 4
            for (int kr = 0; kr < 17; kr++) {
                const int k = 4 * kr;
                ulonglong2 a[4];
#pragma unroll
                for (int i = 0; i < 4; i++)
                    a[i] = *(const ulonglong2*)(gb + FEATO + (4*rg + i)*68 + k);
#pragma unroll
                for (int j = 0; j < 4; j++) {
                    ulonglong2 wv = *(const ulonglong2*)(sm + W1T + (cg + 16*j)*68 + k);
#pragma unroll
                    for (int i = 0; i < 4; i++) {
                        acc[i][j] = fma2(a[i].x, wv.x, acc[i][j]);
                        acc[i][j] = fma2(a[i].y, wv.y, acc[i][j]);
                    }
                }
            }
#pragma unroll
            for (int i = 0; i < 4; i++)
#pragma unroll
                for (int j = 0; j < 4; j++) {
                    float lo, hi; up2(acc[i][j], lo, hi);
                    gb[H1OO + (4*rg + i)*68 + cg + 16*j] =
                        fmaxf(__fadd_rn(lo, hi), 0.0f);
                }
        }
        gbar(bid);

        // ---- layer 2: K=64, 16 rounds ----
        {
            u64 acc[4][4];
#pragma unroll
            for (int i = 0; i < 4; i++)
#pragma unroll
                for (int j = 0; j < 4; j++)
                    acc[i][j] = pk2(sm[B2O + cg + 16*j], 0.0f);
#pragma unroll 4
            for (int kr = 0; kr < 16; kr++) {
                const int k = 4 * kr;
                ulonglong2 a[4];
#pragma unroll
                for (int i = 0; i < 4; i++)
                    a[i] = *(const ulonglong2*)(gb + H1OO + (4*rg + i)*68 + k);
#pragma unroll
                for (int j = 0; j < 4; j++) {
                    ulonglong2 wv = *(const ulonglong2*)(sm + W2T + (cg + 16*j)*68 + k);
#pragma unroll
                    for (int i = 0; i < 4; i++) {
                        acc[i][j] = fma2(a[i].x, wv.x, acc[i][j]);
                        acc[i][j] = fma2(a[i].y, wv.y, acc[i][j]);
                    }
                }
            }
#pragma unroll
            for (int i = 0; i < 4; i++)
#pragma unroll
                for (int j = 0; j < 4; j++) {
                    float lo, hi; up2(acc[i][j], lo, hi);
                    gb[H2OO + (4*rg + i)*68 + cg + 16*j] =
                        fmaxf(__fadd_rn(lo, hi), 0.0f);
                }
        }
        gbar(bid);

        // ---- layer 3: K=64, 128 cols, relu + max over own 4 rows ----
        {
            u64 acc[4][8];
#pragma unroll
            for (int i = 0; i < 4; i++)
#pragma unroll
                for (int j = 0; j < 8; j++)
                    acc[i][j] = pk2(sm[B3O + cg + 16*j], 0.0f);
#pragma unroll 2
            for (int kr = 0; kr < 16; kr++) {
                const int k = 4 * kr;
                ulonglong2 a[4];
#pragma unroll
                for (int i = 0; i < 4; i++)
                    a[i] = *(const ulonglong2*)(gb + H2OO + (4*rg + i)*68 + k);
#pragma unroll
                for (int j = 0; j < 8; j++) {
                    ulonglong2 wv = *(const ulonglong2*)(sm + W3T + (cg + 16*j)*68 + k);
#pragma unroll
                    for (int i = 0; i < 4; i++) {
                        acc[i][j] = fma2(a[i].x, wv.x, acc[i][j]);
                        acc[i][j] = fma2(a[i].y, wv.y, acc[i][j]);
                    }
                }
            }
#pragma unroll
            for (int j = 0; j < 8; j++) {
                float lo, hi; up2(acc[0][j], lo, hi);
                float mm = fmaxf(__fadd_rn(lo, hi), 0.0f);
#pragma unroll
                for (int i = 1; i < 4; i++) {
                    up2(acc[i][j], lo, hi);
                    mm = fmaxf(mm, fmaxf(__fadd_rn(lo, hi), 0.0f));
                }
                gb[ROO + rg*128 + cg + 16*j] = mm;
            }
        }
        gbar(bid);

        if (lt < 128) {
            float mm = gb[ROO + lt];
#pragma unroll
            for (int r = 1; r < 16; r++) mm = fmaxf(mm, gb[ROO + r*128 + lt]);
            dout[(size_t)g * 128 + lt] = mm;
        }
        gbar(bid);   // protect smem reuse next iteration
    }
}

// ============================================================================
extern "C" void kernel_launch(void* const* d_in, const int* in_sizes, int n_in,
                              void* d_out, int out_size)
{
    const float* x   = (const float*)d_in[0];
    const float* pos = (const float*)d_in[1];
    const float* W1 = (const float*)d_in[3];
    const float* b1 = (const float*)d_in[4];
    const float* W2 = (const float*)d_in[5];
    const float* b2 = (const float*)d_in[6];
    const float* W3 = (const float*)d_in[7];
    const float* b3 = (const float*)d_in[8];
    float* out = (float*)d_out;

    const int fused_smem = SM_TOT * sizeof(float);   // 196,224 B -> 1 CTA/SM
    cudaFuncSetAttribute(fused_kernel, cudaFuncAttributeMaxDynamicSharedMemorySize,
                         fused_smem);

    init_kernel<<<(BATCH * NPTS + 255) / 256, 256>>>(pos);
    fused_kernel<<<148, 512, fused_smem>>>(x, pos, W1, b1, W2, b2, W3, b3,
                                           out, out_size);
}